// round 3
// baseline (speedup 1.0000x reference)
#include <cuda_runtime.h>
#include <cuda_bf16.h>
#include <math.h>

// ---- Physical constants, folded at compile time ----
namespace mk {
constexpr double R_      = 3.0 * 0.0254;
constexpr double LSUM    = 0.129907 + 0.095724;
constexpr double G_      = 13.7;
constexpr double MASS_   = 12.0;
constexpr double MOI_    = MASS_ * (12.0 * 0.0254) * (12.0 * 0.0254) / 6.0;

constexpr float INV_R  = (float)(1.0 / R_);
constexpr float L_R    = (float)(LSUM / R_);
constexpr float T_DUTY = (float)(0.193 * G_);
constexpr float T_VEL  = (float)(G_ * 0.000304 * G_);
constexpr float T_FRIC = (float)(0.00317 * G_);
constexpr float K_XY   = (float)(1.0 / (4.0 * R_ * MASS_));
constexpr float K_W    = (float)(1.0 / (4.0 * LSUM * R_ * MOI_));
constexpr float EPS    = 0.01f;
}

// Fast MUFU-path math. Inputs are N(0,1): |theta| <~ 5.5, where MUFU.SIN/COS
// have ~1e-6 abs error; tolerance is 1e-3 rel, current margin 1e4x.
__device__ __forceinline__ void fast_sincos(float x, float& s, float& c) {
    asm("sin.approx.f32 %0, %1;" : "=f"(s) : "f"(x));
    asm("cos.approx.f32 %0, %1;" : "=f"(c) : "f"(x));
}
__device__ __forceinline__ float fast_rsqrt(float x) {
    float r;
    asm("rsqrt.approx.f32 %0, %1;" : "=f"(r) : "f"(x));
    return r;
}

__device__ __forceinline__ void mecanum_row(
    float theta, float vx, float vy, float wz,
    float u0, float u1, float u2,
    float& ax, float& ay, float& aw)
{
    float st, ct;
    fast_sincos(theta, st, ct);

    // local velocity (rotation by -theta)
    float lvx =  ct * vx + st * vy;
    float lvy = -st * vx + ct * vy;

    // wheel velocities
    float p = mk::INV_R * (lvx + lvy);
    float m = mk::INV_R * (lvx - lvy);
    float lz = mk::L_R * wz;
    float w0 = m - lz;
    float w1 = p + lz;
    float w2 = p - lz;
    float w3 = m + lz;

    // motor duty
    float m0 = u0 - u1 - u2;
    float m1 = u0 + u1 + u2;
    float m2 = u0 + u1 - u2;
    float m3 = u0 - u1 + u2;

    // wheel torque
    float t0 = mk::T_DUTY * m0 - mk::T_VEL * w0 - mk::T_FRIC * (w0 * fast_rsqrt(w0 * w0 + mk::EPS));
    float t1 = mk::T_DUTY * m1 - mk::T_VEL * w1 - mk::T_FRIC * (w1 * fast_rsqrt(w1 * w1 + mk::EPS));
    float t2 = mk::T_DUTY * m2 - mk::T_VEL * w2 - mk::T_FRIC * (w2 * fast_rsqrt(w2 * w2 + mk::EPS));
    float t3 = mk::T_DUTY * m3 - mk::T_VEL * w3 - mk::T_FRIC * (w3 * fast_rsqrt(w3 * w3 + mk::EPS));

    // local acceleration (analytic pinv of the 4x3 wheel matrix)
    float la0 = mk::K_XY * ( t0 + t1 + t2 + t3);
    float la1 = mk::K_XY * (-t0 + t1 + t2 - t3);
    float la2 = mk::K_W  * (-t0 + t1 - t2 + t3);

    // rotate back by +theta (A^T)
    ax = ct * la0 - st * la1;
    ay = st * la0 + ct * la1;
    aw = la2;
}

// ---- Warp-sliced smem-staged kernel ----
// 256 threads = 8 warps; each WARP owns 128 consecutive rows and stages them
// through its private smem slice; only __syncwarp() between phases, so warps
// pipeline against each other instead of lock-stepping on block barriers.
// Odd smem strides (25/13) => compute-phase LDS is bank-conflict-free, and
// the load/store-phase scatter is at worst 2-way.
constexpr int THREADS      = 256;
constexpr int WARPS        = THREADS / 32;
constexpr int ROWS_PER_BLK = 4 * THREADS;   // 1024
constexpr int SSTRIDE      = 25;            // 24 state floats + 1 pad
constexpr int CSTRIDE      = 13;            // 12 ctrl  floats + 1 pad
// smem: 256*25*4 + 256*13*4 = 25600 + 13312 = 38912 B -> 6 CTAs/SM at 228KB

__global__ void __launch_bounds__(THREADS)
mecanum_smem_kernel(const float4* __restrict__ st4,
                    const float4* __restrict__ cd4,
                    float4* __restrict__ out4,
                    int B)
{
    __shared__ float s_s[THREADS * SSTRIDE];
    __shared__ float s_c[THREADS * CSTRIDE];

    const int t    = threadIdx.x;
    const int w    = t >> 5;      // warp id
    const int lane = t & 31;

    const long long nsf4 = (long long)B * 6 / 4;
    const long long ncf4 = (long long)B * 3 / 4;
    // this warp's global float4 bases (state / ctrl) and row base
    const long long wsb = (long long)blockIdx.x * (ROWS_PER_BLK * 6 / 4) + (long long)w * 192;
    const long long wcb = (long long)blockIdx.x * (ROWS_PER_BLK * 3 / 4) + (long long)w * 96;
    const long long wrow0 = (long long)blockIdx.x * ROWS_PER_BLK + (long long)w * 128;

    const int ss_base = w * 32 * SSTRIDE;   // warp's smem slice (state)
    const int sc_base = w * 32 * CSTRIDE;   // warp's smem slice (ctrl)

    // ---- Phase 1: coalesced global -> smem (warp-local transpose) ----
#pragma unroll
    for (int k = 0; k < 6; k++) {
        long long f = wsb + lane + 32 * k;
        if (f < nsf4) {
            float4 v = st4[f];
            int lf   = lane + 32 * k;      // local float4 idx within warp slice
            int g    = lf / 6;             // owning lane
            int off  = (lf % 6) * 4;
            int base = ss_base + g * SSTRIDE + off;
            s_s[base + 0] = v.x; s_s[base + 1] = v.y;
            s_s[base + 2] = v.z; s_s[base + 3] = v.w;
        }
    }
#pragma unroll
    for (int k = 0; k < 3; k++) {
        long long f = wcb + lane + 32 * k;
        if (f < ncf4) {
            float4 v = cd4[f];
            int lf   = lane + 32 * k;
            int g    = lf / 3;
            int off  = (lf % 3) * 4;
            int base = sc_base + g * CSTRIDE + off;
            s_c[base + 0] = v.x; s_c[base + 1] = v.y;
            s_c[base + 2] = v.z; s_c[base + 3] = v.w;
        }
    }
    __syncwarp();

    // ---- Phase 2: compute this lane's 4 rows, in place ----
    const int sbase = ss_base + lane * SSTRIDE;
    const int cbase = sc_base + lane * CSTRIDE;
#pragma unroll
    for (int r = 0; r < 4; r++) {
        long long row = wrow0 + 4LL * lane + r;
        if (row < B) {
            int so = sbase + 6 * r;
            int co = cbase + 3 * r;
            float theta = s_s[so + 2];
            float vx = s_s[so + 3], vy = s_s[so + 4], wz = s_s[so + 5];
            float ax, ay, aw;
            mecanum_row(theta, vx, vy, wz,
                        s_c[co + 0], s_c[co + 1], s_c[co + 2],
                        ax, ay, aw);
            s_s[so + 0] = vx; s_s[so + 1] = vy; s_s[so + 2] = wz;
            s_s[so + 3] = ax; s_s[so + 4] = ay; s_s[so + 5] = aw;
        }
    }
    __syncwarp();

    // ---- Phase 3: coalesced smem -> global ----
#pragma unroll
    for (int k = 0; k < 6; k++) {
        long long f = wsb + lane + 32 * k;
        if (f < nsf4) {
            int lf   = lane + 32 * k;
            int g    = lf / 6;
            int off  = (lf % 6) * 4;
            int base = ss_base + g * SSTRIDE + off;
            float4 v;
            v.x = s_s[base + 0]; v.y = s_s[base + 1];
            v.z = s_s[base + 2]; v.w = s_s[base + 3];
            out4[f] = v;
        }
    }
}

// Scalar fallback (only if B % 4 != 0)
__global__ void __launch_bounds__(256)
mecanum1_kernel(const float* __restrict__ state,
                const float* __restrict__ ctrl,
                float* __restrict__ out,
                int B)
{
    int i = blockIdx.x * blockDim.x + threadIdx.x;
    if (i >= B) return;
    const float* s = state + 6 * (size_t)i;
    const float* u = ctrl + 3 * (size_t)i;
    float* o = out + 6 * (size_t)i;
    float ax, ay, aw;
    mecanum_row(s[2], s[3], s[4], s[5], u[0], u[1], u[2], ax, ay, aw);
    o[0] = s[3]; o[1] = s[4]; o[2] = s[5];
    o[3] = ax;   o[4] = ay;   o[5] = aw;
}

extern "C" void kernel_launch(void* const* d_in, const int* in_sizes, int n_in,
                              void* d_out, int out_size)
{
    // metadata order: t (1), state (B*6), control_duty (B*3)
    const float* state = (const float*)d_in[1];
    const float* ctrl  = (const float*)d_in[2];
    float* out = (float*)d_out;
    int B = in_sizes[1] / 6;

    if ((B & 3) == 0) {
        int blocks = (B + ROWS_PER_BLK - 1) / ROWS_PER_BLK;
        mecanum_smem_kernel<<<blocks, THREADS>>>(
            (const float4*)state, (const float4*)ctrl, (float4*)out, B);
    } else {
        int threads = 256;
        int blocks = (B + threads - 1) / threads;
        mecanum1_kernel<<<blocks, threads>>>(state, ctrl, out, B);
    }
}

// round 4
// speedup vs baseline: 1.4662x; 1.4662x over previous
#include <cuda_runtime.h>
#include <cuda_bf16.h>
#include <math.h>

// ---- Physical constants, folded at compile time ----
namespace mk {
constexpr double R_      = 3.0 * 0.0254;
constexpr double LSUM    = 0.129907 + 0.095724;
constexpr double G_      = 13.7;
constexpr double MASS_   = 12.0;
constexpr double MOI_    = MASS_ * (12.0 * 0.0254) * (12.0 * 0.0254) / 6.0;

constexpr float INV_R  = (float)(1.0 / R_);
constexpr float L_R    = (float)(LSUM / R_);
constexpr float T_DUTY = (float)(0.193 * G_);
constexpr float T_VEL  = (float)(G_ * 0.000304 * G_);
constexpr float T_FRIC = (float)(0.00317 * G_);
constexpr float K_XY   = (float)(1.0 / (4.0 * R_ * MASS_));
constexpr float K_W    = (float)(1.0 / (4.0 * LSUM * R_ * MOI_));
constexpr float EPS    = 0.01f;
}

// MUFU-path math: inputs are N(0,1) (|theta| <~ 5.5) where sin/cos.approx are
// ~1e-6 accurate; tolerance is 1e-3 and we measured 9e-8 with this path.
__device__ __forceinline__ void fast_sincos(float x, float& s, float& c) {
    asm("sin.approx.f32 %0, %1;" : "=f"(s) : "f"(x));
    asm("cos.approx.f32 %0, %1;" : "=f"(c) : "f"(x));
}
__device__ __forceinline__ float fast_rsqrt(float x) {
    float r;
    asm("rsqrt.approx.f32 %0, %1;" : "=f"(r) : "f"(x));
    return r;
}

__device__ __forceinline__ void mecanum_row(
    float theta, float vx, float vy, float wz,
    float u0, float u1, float u2,
    float& ax, float& ay, float& aw)
{
    float st, ct;
    fast_sincos(theta, st, ct);

    // local velocity (rotation by -theta)
    float lvx =  ct * vx + st * vy;
    float lvy = -st * vx + ct * vy;

    // wheel velocities
    float p  = mk::INV_R * (lvx + lvy);
    float m  = mk::INV_R * (lvx - lvy);
    float lz = mk::L_R * wz;
    float w0 = m - lz;
    float w1 = p + lz;
    float w2 = p - lz;
    float w3 = m + lz;

    // motor duty
    float m0 = u0 - u1 - u2;
    float m1 = u0 + u1 + u2;
    float m2 = u0 + u1 - u2;
    float m3 = u0 - u1 + u2;

    // wheel torque
    float t0 = mk::T_DUTY * m0 - mk::T_VEL * w0 - mk::T_FRIC * (w0 * fast_rsqrt(w0 * w0 + mk::EPS));
    float t1 = mk::T_DUTY * m1 - mk::T_VEL * w1 - mk::T_FRIC * (w1 * fast_rsqrt(w1 * w1 + mk::EPS));
    float t2 = mk::T_DUTY * m2 - mk::T_VEL * w2 - mk::T_FRIC * (w2 * fast_rsqrt(w2 * w2 + mk::EPS));
    float t3 = mk::T_DUTY * m3 - mk::T_VEL * w3 - mk::T_FRIC * (w3 * fast_rsqrt(w3 * w3 + mk::EPS));

    // local acceleration (analytic pinv of the 4x3 wheel matrix)
    float la0 = mk::K_XY * ( t0 + t1 + t2 + t3);
    float la1 = mk::K_XY * (-t0 + t1 + t2 - t3);
    float la2 = mk::K_W  * (-t0 + t1 - t2 + t3);

    // rotate back by +theta (A^T)
    ax = ct * la0 - st * la1;
    ay = st * la0 + ct * la1;
    aw = la2;
}

// ---- One row per thread, direct global access, max occupancy ----
// Alignment facts (bytes): state row i starts at 24i.
//   (theta,vx) at 24i+8  -> 8-aligned  -> float2 load
//   (vy,wz)    at 24i+16 -> 8-aligned  -> float2 load
//   state[0..1] (x,y) are NEVER loaded (unused by the model).
//   ctrl row at 12i -> only 4-aligned  -> 3 scalar loads
//   out row at 24i  -> 8-aligned       -> 3 float2 stores
__global__ void __launch_bounds__(256, 8)
mecanum_row_kernel(const float* __restrict__ state,
                   const float* __restrict__ ctrl,
                   float* __restrict__ out,
                   int B)
{
    int i = blockIdx.x * blockDim.x + threadIdx.x;
    if (i >= B) return;

    const float2* s2 = reinterpret_cast<const float2*>(state + 6 * (size_t)i + 2);
    float2 tv = s2[0];          // theta, vx
    float2 vw = s2[1];          // vy, wz

    const float* u = ctrl + 3 * (size_t)i;
    float u0 = u[0], u1 = u[1], u2 = u[2];

    float ax, ay, aw;
    mecanum_row(tv.x, tv.y, vw.x, vw.y, u0, u1, u2, ax, ay, aw);

    float2* o2 = reinterpret_cast<float2*>(out + 6 * (size_t)i);
    o2[0] = make_float2(tv.y, vw.x);   // vx, vy
    o2[1] = make_float2(vw.y, ax);     // wz, ax
    o2[2] = make_float2(ay, aw);       // ay, aw
}

extern "C" void kernel_launch(void* const* d_in, const int* in_sizes, int n_in,
                              void* d_out, int out_size)
{
    // metadata order: t (1), state (B*6), control_duty (B*3)
    const float* state = (const float*)d_in[1];
    const float* ctrl  = (const float*)d_in[2];
    float* out = (float*)d_out;
    int B = in_sizes[1] / 6;

    int threads = 256;
    int blocks = (B + threads - 1) / threads;
    mecanum_row_kernel<<<blocks, threads>>>(state, ctrl, out, B);
}